// round 5
// baseline (speedup 1.0000x reference)
#include <cuda_runtime.h>
#include <cstdint>

// Problem constants (match reference_code)
#define N_ROWS 1000000
#define M_ROWS 2000000
#define DIM    128

// Scratch: segment bounds per output row. 2 * 4 MB static device arrays
// (allowed: __device__ globals, no runtime allocation).
__device__ int g_seg_start[N_ROWS];
__device__ int g_seg_end[N_ROWS];

// ---------------------------------------------------------------------------
// Kernel 1: zero the bound arrays (absent rows -> empty segment [0,0)).
// ---------------------------------------------------------------------------
__global__ void init_bounds_kernel() {
    int n = blockIdx.x * blockDim.x + threadIdx.x;
    if (n < N_ROWS) {
        g_seg_start[n] = 0;
        g_seg_end[n]   = 0;
    }
}

// ---------------------------------------------------------------------------
// Kernel 2: mark segment boundaries from the sorted index array (int32 —
// JAX downcasts int64 to int32 with x64 disabled).
// For each m: if idx[m] != idx[m-1]  -> start of segment for row idx[m]
//             if idx[m] != idx[m+1]  -> end of segment (exclusive)
// Bounds-guarded so a bad index can't produce an illegal access.
// ---------------------------------------------------------------------------
__global__ void mark_bounds_kernel(const int* __restrict__ idx) {
    int m = blockIdx.x * blockDim.x + threadIdx.x;
    if (m >= M_ROWS) return;
    int n = idx[m];
    if (n < 0 || n >= N_ROWS) return;  // defensive: never write OOB
    if (m == 0 || idx[m - 1] != n)          g_seg_start[n] = m;
    if (m == M_ROWS - 1 || idx[m + 1] != n) g_seg_end[n]   = m + 1;
}

// ---------------------------------------------------------------------------
// Kernel 3: one warp per output row. Each lane owns one float4 (4 columns).
// acc = var[row]; for m in [start,end): acc += value[m]; out[row] = acc.
// Fully coalesced 512B row transactions; value rows for consecutive output
// rows are contiguous (indices sorted), so the value stream is sequential.
// ---------------------------------------------------------------------------
__global__ void __launch_bounds__(256) gather_add_kernel(
    const float* __restrict__ var,
    const float* __restrict__ value,
    float* __restrict__ out)
{
    int warp_id = (blockIdx.x * blockDim.x + threadIdx.x) >> 5;
    if (warp_id >= N_ROWS) return;
    int lane = threadIdx.x & 31;

    int lo = g_seg_start[warp_id];
    int hi = g_seg_end[warp_id];

    const float4* vrow = reinterpret_cast<const float4*>(var + (size_t)warp_id * DIM);
    float4 acc = vrow[lane];

    // Average segment length is M/N = 2; unroll by 2 to expose MLP.
    int m = lo;
    for (; m + 1 < hi; m += 2) {
        float4 a = reinterpret_cast<const float4*>(value + (size_t)m * DIM)[lane];
        float4 b = reinterpret_cast<const float4*>(value + (size_t)(m + 1) * DIM)[lane];
        acc.x += a.x + b.x;
        acc.y += a.y + b.y;
        acc.z += a.z + b.z;
        acc.w += a.w + b.w;
    }
    if (m < hi) {
        float4 a = reinterpret_cast<const float4*>(value + (size_t)m * DIM)[lane];
        acc.x += a.x;
        acc.y += a.y;
        acc.z += a.z;
        acc.w += a.w;
    }

    reinterpret_cast<float4*>(out + (size_t)warp_id * DIM)[lane] = acc;
}

// ---------------------------------------------------------------------------
// Launch
// ---------------------------------------------------------------------------
extern "C" void kernel_launch(void* const* d_in, const int* in_sizes, int n_in,
                              void* d_out, int out_size) {
    const float* var   = (const float*)d_in[0];   // [N, 128] f32
    const float* value = (const float*)d_in[1];   // [M, 128] f32
    const int*   sidx  = (const int*)d_in[2];     // [M] i32 (JAX x64-off), sorted
    // d_in[3] = pos (unused)
    float* out = (float*)d_out;                   // [N, 128] f32

    {
        int threads = 256;
        int blocks = (N_ROWS + threads - 1) / threads;
        init_bounds_kernel<<<blocks, threads>>>();
    }
    {
        int threads = 256;
        int blocks = (M_ROWS + threads - 1) / threads;
        mark_bounds_kernel<<<blocks, threads>>>(sidx);
    }
    {
        int threads = 256;                       // 8 warps per block
        int warps_per_block = threads / 32;
        int blocks = (N_ROWS + warps_per_block - 1) / warps_per_block;
        gather_add_kernel<<<blocks, threads>>>(var, value, out);
    }
}

// round 6
// speedup vs baseline: 1.1189x; 1.1189x over previous
#include <cuda_runtime.h>
#include <cstdint>

// Problem constants (match reference_code)
#define N_ROWS 1000000
#define M_ROWS 2000000
#define DIM    128

// Scratch: fused segment bounds per output row: .x = start, .y = end (excl).
// Zeroed each call via cudaMemsetAsync (absent rows -> empty segment [0,0)).
__device__ int2 g_seg[N_ROWS];

// ---------------------------------------------------------------------------
// Kernel 1: mark segment boundaries from the sorted int32 index array.
// For each m: if idx[m] != idx[m-1]  -> start of segment for row idx[m]
//             if idx[m] != idx[m+1]  -> end of segment (exclusive)
// Bounds-guarded so a bad index can't produce an illegal access.
// ---------------------------------------------------------------------------
__global__ void mark_bounds_kernel(const int* __restrict__ idx) {
    int m = blockIdx.x * blockDim.x + threadIdx.x;
    if (m >= M_ROWS) return;
    int n = idx[m];
    if (n < 0 || n >= N_ROWS) return;  // defensive: never write OOB
    if (m == 0 || idx[m - 1] != n)          g_seg[n].x = m;
    if (m == M_ROWS - 1 || idx[m + 1] != n) g_seg[n].y = m + 1;
}

// ---------------------------------------------------------------------------
// Kernel 2: one warp per output row. Each lane owns one float4 (4 columns).
// acc = var[row]; for m in [start,end): acc += value[m]; out[row] = acc.
// All three big streams are use-once: __ldcs / __stcs (evict-first) keeps
// them from churning L2. Fully coalesced 512B row transactions; value rows
// for consecutive output rows are contiguous (indices sorted).
// ---------------------------------------------------------------------------
__global__ void __launch_bounds__(256) gather_add_kernel(
    const float* __restrict__ var,
    const float* __restrict__ value,
    float* __restrict__ out)
{
    int warp_id = (blockIdx.x * blockDim.x + threadIdx.x) >> 5;
    if (warp_id >= N_ROWS) return;
    int lane = threadIdx.x & 31;

    // One 8-byte load for both bounds.
    int2 seg = __ldg(&g_seg[warp_id]);
    int lo = seg.x, hi = seg.y;

    const float4* vrow = reinterpret_cast<const float4*>(var + (size_t)warp_id * DIM);
    float4 acc = __ldcs(&vrow[lane]);

    // Average segment length is M/N = 2; unroll by 2 to expose MLP.
    int m = lo;
    for (; m + 1 < hi; m += 2) {
        float4 a = __ldcs(&reinterpret_cast<const float4*>(value + (size_t)m * DIM)[lane]);
        float4 b = __ldcs(&reinterpret_cast<const float4*>(value + (size_t)(m + 1) * DIM)[lane]);
        acc.x += a.x + b.x;
        acc.y += a.y + b.y;
        acc.z += a.z + b.z;
        acc.w += a.w + b.w;
    }
    if (m < hi) {
        float4 a = __ldcs(&reinterpret_cast<const float4*>(value + (size_t)m * DIM)[lane]);
        acc.x += a.x;
        acc.y += a.y;
        acc.z += a.z;
        acc.w += a.w;
    }

    __stcs(&reinterpret_cast<float4*>(out + (size_t)warp_id * DIM)[lane], acc);
}

// ---------------------------------------------------------------------------
// Launch
// ---------------------------------------------------------------------------
extern "C" void kernel_launch(void* const* d_in, const int* in_sizes, int n_in,
                              void* d_out, int out_size) {
    const float* var   = (const float*)d_in[0];   // [N, 128] f32
    const float* value = (const float*)d_in[1];   // [M, 128] f32
    const int*   sidx  = (const int*)d_in[2];     // [M] i32 (JAX x64-off), sorted
    // d_in[3] = pos (unused)
    float* out = (float*)d_out;                   // [N, 128] f32

    // Zero bounds via memset node (graph-capturable, ~1.3us at mem speed).
    void* seg_ptr = nullptr;
    cudaGetSymbolAddress(&seg_ptr, g_seg);
    cudaMemsetAsync(seg_ptr, 0, sizeof(int2) * (size_t)N_ROWS);

    {
        int threads = 256;
        int blocks = (M_ROWS + threads - 1) / threads;
        mark_bounds_kernel<<<blocks, threads>>>(sidx);
    }
    {
        int threads = 256;                       // 8 warps per block
        int warps_per_block = threads / 32;
        int blocks = (N_ROWS + warps_per_block - 1) / warps_per_block;
        gather_add_kernel<<<blocks, threads>>>(var, value, out);
    }
}

// round 8
// speedup vs baseline: 1.1443x; 1.0227x over previous
#include <cuda_runtime.h>
#include <cstdint>

// Problem constants (match reference_code)
#define N_ROWS 1000000
#define M_ROWS 2000000
#define DIM    128

// CSR-style row offsets: offsets[r] = lower_bound(sorted_indices, r).
// Segment for output row n = [offsets[n], offsets[n+1]).
// Every entry is written by build_offsets_kernel -> no zero-init needed.
__device__ int g_offsets[N_ROWS + 1];

// ---------------------------------------------------------------------------
// Kernel 1: build the full offsets array from the sorted int32 index array.
// Thread m (0..M inclusive):
//   m == 0      : offsets[r] = 0 for r in [0, idx[0]]
//   m == M      : offsets[r] = M for r in (idx[M-1], N]
//   else if idx[m] != idx[m-1]: offsets[r] = m for r in (idx[m-1], idx[m]]
// Each offsets entry is written exactly once. Gap loops are short for
// near-uniform sorted indices (total writes across all threads = N+1).
// ---------------------------------------------------------------------------
__global__ void build_offsets_kernel(const int* __restrict__ idx) {
    int m = blockIdx.x * blockDim.x + threadIdx.x;
    if (m > M_ROWS) return;

    if (m == 0) {
        int first = idx[0];
        if (first < 0) first = 0;
        if (first > N_ROWS - 1) first = N_ROWS - 1;
        for (int r = 0; r <= first; ++r) g_offsets[r] = 0;
    } else if (m == M_ROWS) {
        int last = idx[M_ROWS - 1];
        if (last < 0) last = 0;
        if (last > N_ROWS - 1) last = N_ROWS - 1;
        for (int r = last + 1; r <= N_ROWS; ++r) g_offsets[r] = M_ROWS;
    } else {
        int cur  = idx[m];
        int prev = idx[m - 1];
        if (cur != prev) {
            // defensive clamps: never write outside [0, N_ROWS]
            if (prev < -1) prev = -1;
            if (cur > N_ROWS - 1) cur = N_ROWS - 1;
            for (int r = prev + 1; r <= cur; ++r) g_offsets[r] = m;
        }
    }
}

// ---------------------------------------------------------------------------
// Kernel 2: one warp per output row. Each lane owns one float4 (4 columns).
// acc = var[row]; for m in [lo,hi): acc += value[m]; out[row] = acc.
// All three big streams are use-once: __ldcs / __stcs (evict-first).
// Offsets reads are uniform per warp and L2-resident (4 MB, just written).
// ---------------------------------------------------------------------------
__global__ void __launch_bounds__(256) gather_add_kernel(
    const float* __restrict__ var,
    const float* __restrict__ value,
    float* __restrict__ out)
{
    int warp_id = (blockIdx.x * blockDim.x + threadIdx.x) >> 5;
    if (warp_id >= N_ROWS) return;
    int lane = threadIdx.x & 31;

    int lo = __ldg(&g_offsets[warp_id]);
    int hi = __ldg(&g_offsets[warp_id + 1]);

    const float4* vrow = reinterpret_cast<const float4*>(var + (size_t)warp_id * DIM);
    float4 acc = __ldcs(&vrow[lane]);

    // Average segment length is M/N = 2; unroll by 2 to expose MLP.
    int m = lo;
    for (; m + 1 < hi; m += 2) {
        float4 a = __ldcs(&reinterpret_cast<const float4*>(value + (size_t)m * DIM)[lane]);
        float4 b = __ldcs(&reinterpret_cast<const float4*>(value + (size_t)(m + 1) * DIM)[lane]);
        acc.x += a.x + b.x;
        acc.y += a.y + b.y;
        acc.z += a.z + b.z;
        acc.w += a.w + b.w;
    }
    if (m < hi) {
        float4 a = __ldcs(&reinterpret_cast<const float4*>(value + (size_t)m * DIM)[lane]);
        acc.x += a.x;
        acc.y += a.y;
        acc.z += a.z;
        acc.w += a.w;
    }

    __stcs(&reinterpret_cast<float4*>(out + (size_t)warp_id * DIM)[lane], acc);
}

// ---------------------------------------------------------------------------
// Launch
// ---------------------------------------------------------------------------
extern "C" void kernel_launch(void* const* d_in, const int* in_sizes, int n_in,
                              void* d_out, int out_size) {
    const float* var   = (const float*)d_in[0];   // [N, 128] f32
    const float* value = (const float*)d_in[1];   // [M, 128] f32
    const int*   sidx  = (const int*)d_in[2];     // [M] i32 (JAX x64-off), sorted
    // d_in[3] = pos (unused)
    float* out = (float*)d_out;                   // [N, 128] f32

    {
        int threads = 256;
        int blocks = (M_ROWS + 1 + threads - 1) / threads;  // M+1 threads
        build_offsets_kernel<<<blocks, threads>>>(sidx);
    }
    {
        int threads = 256;                       // 8 warps per block
        int warps_per_block = threads / 32;
        int blocks = (N_ROWS + warps_per_block - 1) / warps_per_block;
        gather_add_kernel<<<blocks, threads>>>(var, value, out);
    }
}